// round 1
// baseline (speedup 1.0000x reference)
#include <cuda_runtime.h>
#include <cstddef>

typedef unsigned long long ull;

// ---------------------------------------------------------------------------
// Packed f32x2 helpers (Blackwell sm_100+)
// ---------------------------------------------------------------------------
__device__ __forceinline__ ull bcast2(float a) {
    ull r; asm("mov.b64 %0, {%1, %1};" : "=l"(r) : "f"(a)); return r;
}
__device__ __forceinline__ void unpack2(ull v, float& a, float& b) {
    asm("mov.b64 {%0, %1}, %2;" : "=f"(a), "=f"(b) : "l"(v));
}
__device__ __forceinline__ ull fma2(ull a, ull b, ull c) {
    ull d; asm("fma.rn.f32x2 %0, %1, %2, %3;" : "=l"(d) : "l"(a), "l"(b), "l"(c));
    return d;
}
__device__ __forceinline__ float ex2_fast(float x) {
    float r; asm("ex2.approx.f32 %0, %1;" : "=f"(r) : "f"(x)); return r;
}
__device__ __forceinline__ float rcp_fast(float x) {
    float r; asm("rcp.approx.f32 %0, %1;" : "=f"(r) : "f"(x)); return r;
}
// accurate-enough tanh: 1 - 2/(e^{2z}+1), built from ex2/rcp (~1e-6 rel err)
__device__ __forceinline__ float tanh_acc(float z) {
    float e = ex2_fast(2.8853900817779268f * z);   // e^{2z}
    float r = rcp_fast(e + 1.0f);
    return fmaf(-2.0f, r, 1.0f);
}

// ---------------------------------------------------------------------------
// Shared-memory layout (floats), per coupling layer, per net (stride 2944):
//   [0)      W1half  [64][16]   (rows MOFF..MOFF+63 of W1)
//   [1024)   b1      [16]
//   [1040)   W2      [16][16]
//   [1296)   b2      [16]
//   [1312)   W3      [16][16]
//   [1568)   b3      [16]
//   [1584)   W4      [16][16]
//   [1840)   b4      [16]
//   [1856)   W5half  [16][64]   (cols UOFF..UOFF+63 of W5)
//   [2880)   b5half  [64]
// Layer block = 2 nets (t then s) = 5888 floats. 6 layers = 35328 floats.
// ---------------------------------------------------------------------------
#define NET_STRIDE   2944
#define LAYER_STRIDE 5888
#define SMEM_FLOATS  35328
#define SMEM_BYTES   (SMEM_FLOATS * 4)

__device__ void load_net(float* L,
                         const float* W1, const float* b1,
                         const float* W2, const float* b2,
                         const float* W3, const float* b3,
                         const float* W4, const float* b4,
                         const float* W5, const float* b5,
                         int MOFF, int UOFF) {
    const int t = threadIdx.x;
    const int nt = blockDim.x;
    for (int idx = t; idx < 1024; idx += nt) L[idx] = W1[(MOFF << 4) + idx];
    for (int idx = t; idx < 16;   idx += nt) L[1024 + idx] = b1[idx];
    for (int idx = t; idx < 256;  idx += nt) L[1040 + idx] = W2[idx];
    for (int idx = t; idx < 16;   idx += nt) L[1296 + idx] = b2[idx];
    for (int idx = t; idx < 256;  idx += nt) L[1312 + idx] = W3[idx];
    for (int idx = t; idx < 16;   idx += nt) L[1568 + idx] = b3[idx];
    for (int idx = t; idx < 256;  idx += nt) L[1584 + idx] = W4[idx];
    for (int idx = t; idx < 16;   idx += nt) L[1840 + idx] = b4[idx];
    for (int idx = t; idx < 1024; idx += nt)
        L[1856 + idx] = W5[(idx >> 6) * 128 + UOFF + (idx & 63)];
    for (int idx = t; idx < 64;   idx += nt) L[2880 + idx] = b5[UOFF + idx];
}

// ---------------------------------------------------------------------------
// Hidden stack of one net: h = relu(...relu(relu(xm@W1+b1)@W2+b2)...@W4+b4)
// ---------------------------------------------------------------------------
template<int MOFF>
__device__ __forceinline__ void net_hidden(const float (&x)[128],
                                           const float* __restrict__ sw,
                                           float (&h)[16]) {
    // layer 1: 64 -> 16
    {
        const ull* W = (const ull*)sw;
        const ull* b = (const ull*)(sw + 1024);
        ull acc[8];
        #pragma unroll
        for (int j = 0; j < 8; j++) acc[j] = b[j];
        #pragma unroll
        for (int k = 0; k < 64; k++) {
            ull xk = bcast2(x[MOFF + k]);
            #pragma unroll
            for (int j = 0; j < 8; j++) acc[j] = fma2(xk, W[k * 8 + j], acc[j]);
        }
        #pragma unroll
        for (int j = 0; j < 8; j++) {
            float a, bb; unpack2(acc[j], a, bb);
            h[2 * j]     = fmaxf(a, 0.0f);
            h[2 * j + 1] = fmaxf(bb, 0.0f);
        }
    }
    // layers 2..4: 16 -> 16
    #pragma unroll
    for (int l = 0; l < 3; l++) {
        const float* base = sw + 1040 + l * 272;
        const ull* W = (const ull*)base;
        const ull* b = (const ull*)(base + 256);
        ull acc[8];
        #pragma unroll
        for (int j = 0; j < 8; j++) acc[j] = b[j];
        #pragma unroll
        for (int k = 0; k < 16; k++) {
            ull hk = bcast2(h[k]);
            #pragma unroll
            for (int j = 0; j < 8; j++) acc[j] = fma2(hk, W[k * 8 + j], acc[j]);
        }
        #pragma unroll
        for (int j = 0; j < 8; j++) {
            float a, bb; unpack2(acc[j], a, bb);
            h[2 * j]     = fmaxf(a, 0.0f);
            h[2 * j + 1] = fmaxf(bb, 0.0f);
        }
    }
}

// ---------------------------------------------------------------------------
// One coupling layer (inverse direction):
//   x_u = (x_u - t_u) * exp(-s_u)   for u in unmasked half; ld -= sum(s)
// ---------------------------------------------------------------------------
template<int MOFF>
__device__ __forceinline__ void coupling(float (&x)[128], float& ld,
                                         const float* __restrict__ sw) {
    constexpr int UOFF = 64 - MOFF;
    float h[16];

    // ---- t net: subtract linear head from unmasked half ----
    net_hidden<MOFF>(x, sw, h);
    {
        const ull* W5 = (const ull*)(sw + 1856);
        const ull* b5 = (const ull*)(sw + 2880);
        #pragma unroll
        for (int c = 0; c < 4; c++) {          // 4 chunks of 16 outputs
            ull acc[8];
            #pragma unroll
            for (int u = 0; u < 8; u++) acc[u] = b5[c * 8 + u];
            #pragma unroll
            for (int k = 0; k < 16; k++) {
                ull hk = bcast2(h[k]);
                #pragma unroll
                for (int u = 0; u < 8; u++)
                    acc[u] = fma2(hk, W5[k * 32 + c * 8 + u], acc[u]);
            }
            #pragma unroll
            for (int u = 0; u < 8; u++) {
                float a, bb; unpack2(acc[u], a, bb);
                x[UOFF + c * 16 + 2 * u]     -= a;
                x[UOFF + c * 16 + 2 * u + 1] -= bb;
            }
        }
    }

    // ---- s net: scale by exp(-tanh(head)), accumulate logdet ----
    const float* ss = sw + NET_STRIDE;
    net_hidden<MOFF>(x, ss, h);
    {
        const ull* W5 = (const ull*)(ss + 1856);
        const ull* b5 = (const ull*)(ss + 2880);
        #pragma unroll
        for (int c = 0; c < 4; c++) {
            ull acc[8];
            #pragma unroll
            for (int u = 0; u < 8; u++) acc[u] = b5[c * 8 + u];
            #pragma unroll
            for (int k = 0; k < 16; k++) {
                ull hk = bcast2(h[k]);
                #pragma unroll
                for (int u = 0; u < 8; u++)
                    acc[u] = fma2(hk, W5[k * 32 + c * 8 + u], acc[u]);
            }
            #pragma unroll
            for (int u = 0; u < 8; u++) {
                float a, bb; unpack2(acc[u], a, bb);
                float s0 = tanh_acc(a);
                float s1 = tanh_acc(bb);
                x[UOFF + c * 16 + 2 * u]     *= ex2_fast(-1.4426950408889634f * s0);
                x[UOFF + c * 16 + 2 * u + 1] *= ex2_fast(-1.4426950408889634f * s1);
                ld -= (s0 + s1);
            }
        }
    }
}

// ---------------------------------------------------------------------------
// Fused kernel: stage all pruned weights in smem, then grid-stride over rows
// with the entire 6-layer flow in registers.
// ---------------------------------------------------------------------------
__global__ void __launch_bounds__(256, 1)
realnvp_kernel(const float* __restrict__ x_in,
               const float* __restrict__ tW1, const float* __restrict__ tb1,
               const float* __restrict__ tW2, const float* __restrict__ tb2,
               const float* __restrict__ tW3, const float* __restrict__ tb3,
               const float* __restrict__ tW4, const float* __restrict__ tb4,
               const float* __restrict__ tW5, const float* __restrict__ tb5,
               const float* __restrict__ sW1, const float* __restrict__ sb1,
               const float* __restrict__ sW2, const float* __restrict__ sb2,
               const float* __restrict__ sW3, const float* __restrict__ sb3,
               const float* __restrict__ sW4, const float* __restrict__ sb4,
               const float* __restrict__ sW5, const float* __restrict__ sb5,
               float* __restrict__ y_out, float* __restrict__ ld_out, int B) {
    extern __shared__ float smw[];

    // Stage pruned weights. Processed layer i uses original layer p = 5-i.
    // i even -> mask ones on [0,64)  -> MOFF=0,  UOFF=64
    // i odd  -> mask ones on [64,128)-> MOFF=64, UOFF=0
    #pragma unroll 1
    for (int i = 0; i < 6; i++) {
        const int p = 5 - i;
        const int MOFF = (i & 1) ? 64 : 0;
        const int UOFF = 64 - MOFF;
        float* L = smw + i * LAYER_STRIDE;
        load_net(L,
                 tW1 + p * 2048, tb1 + p * 16, tW2 + p * 256, tb2 + p * 16,
                 tW3 + p * 256,  tb3 + p * 16, tW4 + p * 256, tb4 + p * 16,
                 tW5 + p * 2048, tb5 + p * 128, MOFF, UOFF);
        load_net(L + NET_STRIDE,
                 sW1 + p * 2048, sb1 + p * 16, sW2 + p * 256, sb2 + p * 16,
                 sW3 + p * 256,  sb3 + p * 16, sW4 + p * 256, sb4 + p * 16,
                 sW5 + p * 2048, sb5 + p * 128, MOFF, UOFF);
    }
    __syncthreads();

    const int stride = gridDim.x * blockDim.x;
    for (int r = blockIdx.x * blockDim.x + threadIdx.x; r < B; r += stride) {
        float x[128];
        const float4* xr = (const float4*)(x_in + (size_t)r * 128);
        #pragma unroll
        for (int q = 0; q < 32; q++) {
            float4 v = xr[q];
            x[4 * q + 0] = v.x; x[4 * q + 1] = v.y;
            x[4 * q + 2] = v.z; x[4 * q + 3] = v.w;
        }
        float ld = 0.0f;
        coupling<0 >(x, ld, smw + 0 * LAYER_STRIDE);
        coupling<64>(x, ld, smw + 1 * LAYER_STRIDE);
        coupling<0 >(x, ld, smw + 2 * LAYER_STRIDE);
        coupling<64>(x, ld, smw + 3 * LAYER_STRIDE);
        coupling<0 >(x, ld, smw + 4 * LAYER_STRIDE);
        coupling<64>(x, ld, smw + 5 * LAYER_STRIDE);

        float4* yr = (float4*)(y_out + (size_t)r * 128);
        #pragma unroll
        for (int q = 0; q < 32; q++)
            yr[q] = make_float4(x[4 * q], x[4 * q + 1], x[4 * q + 2], x[4 * q + 3]);
        ld_out[r] = ld;
    }
}

// ---------------------------------------------------------------------------
// Harness entry point.
// Input order: x, masks, tW1,tb1,...,tW5,tb5, sW1,sb1,...,sW5,sb5
// Output: y [B,128] followed by logdet [B]
// ---------------------------------------------------------------------------
extern "C" void kernel_launch(void* const* d_in, const int* in_sizes, int n_in,
                              void* d_out, int out_size) {
    const float* x = (const float*)d_in[0];
    // d_in[1] = masks (pattern hardcoded: fixed by problem construction)
    const float* P[20];
    for (int i = 0; i < 20; i++) P[i] = (const float*)d_in[2 + i];

    const int B = in_sizes[0] / 128;
    float* y  = (float*)d_out;
    float* ld = y + (size_t)B * 128;

    cudaFuncSetAttribute(realnvp_kernel,
                         cudaFuncAttributeMaxDynamicSharedMemorySize, SMEM_BYTES);

    dim3 grid(148), block(256);
    realnvp_kernel<<<grid, block, SMEM_BYTES>>>(
        x,
        P[0], P[1], P[2], P[3], P[4], P[5], P[6], P[7], P[8], P[9],
        P[10], P[11], P[12], P[13], P[14], P[15], P[16], P[17], P[18], P[19],
        y, ld, B);
}